// round 3
// baseline (speedup 1.0000x reference)
#include <cuda_runtime.h>
#include <cstdint>

// Problem constants
#define Bn 4
#define Cn 32
#define Ln 256
#define Mn 256
#define Fn 8
#define Nn 64
#define FC (Fn * Cn)          // 256
#define LM (Ln * Mn)          // 65536
#define IMAG_OFF ((size_t)Bn * Fn * LM)  // 2,097,152
#define STAGES 8

union U64 {
    unsigned long long u;
    float2 f;
};

__device__ __forceinline__ unsigned long long ffma2(unsigned long long a,
                                                    unsigned long long b,
                                                    unsigned long long c) {
    unsigned long long d;
    asm("fma.rn.f32x2 %0, %1, %2, %3;" : "=l"(d) : "l"(a), "l"(b), "l"(c));
    return d;
}

__device__ __forceinline__ uint32_t smem_u32(const void* p) {
    uint32_t a;
    asm("{ .reg .u64 t; cvta.to.shared.u64 t, %1; cvt.u32.u64 %0, t; }"
        : "=r"(a) : "l"(p));
    return a;
}

__device__ __forceinline__ void cp16(uint32_t smem, const void* gmem) {
    asm volatile("cp.async.cg.shared.global [%0], [%1], 16;"
                 :: "r"(smem), "l"(gmem));
}
__device__ __forceinline__ void cp_commit() {
    asm volatile("cp.async.commit_group;");
}
__device__ __forceinline__ void cp_wait6() {
    asm volatile("cp.async.wait_group 6;");
}

// ---------------------------------------------------------------------------
// Fused kernel, cp.async pipelined over C.
// Grid: B*L = 1024 blocks, 128 threads. Each thread handles 2 consecutive m.
// ---------------------------------------------------------------------------
__global__ __launch_bounds__(128, 7) void sphere_pipe_kernel(
    const float* __restrict__ xr,
    const float* __restrict__ xi,
    const float* __restrict__ wr,
    const float* __restrict__ wi,
    float* __restrict__ out) {
    __shared__ ulonglong2 s2[FC];                 // 4 KB weights
    __shared__ float sx[STAGES][2][Mn];           // 16 KB x ring buffer

    int bid = blockIdx.x;
    int b = bid >> 8;
    int l = bid & (Ln - 1);
    int tid = threadIdx.x;

    // --- interpolate this l's weights into shared ---
    {
        float t = (float)l * (63.0f / 255.0f);
        int lo = (int)t;
        if (lo > Nn - 2) lo = Nn - 2;
        float fr = t - (float)lo;
        float om = 1.0f - fr;
#pragma unroll
        for (int j = 0; j < 2; ++j) {
            int k = tid + j * 128;
            const float* pwr = wr + k * Nn + lo;
            const float* pwi = wi + k * Nn + lo;
            float vr = pwr[0] * om + pwr[1] * fr;
            float vi = pwi[0] * om + pwi[1] * fr;
            U64 ur, ui;
            ur.f = make_float2(vr, vr);
            ui.f = make_float2(vi, vi);
            s2[k] = make_ulonglong2(ur.u, ui.u);
        }
    }

    // --- cp.async setup: thread t<64 copies xr, t>=64 copies xi (16B each) ---
    size_t xbase = (size_t)b * Cn * LM + (size_t)l * Mn;
    int half = tid >> 6;                // 0 -> xr, 1 -> xi
    int off4 = (tid & 63) * 4;          // element offset within the 256-row
    const float* gsrc = (half ? xi : xr) + xbase + off4;
    // stage copy target smem addresses
    uint32_t sdst0 = smem_u32(&sx[0][half][off4]);

    // prologue: issue stages 0 .. STAGES-2
#pragma unroll
    for (int s = 0; s < STAGES - 1; ++s) {
        cp16(sdst0 + s * (2 * Mn * 4), gsrc + (size_t)s * LM);
        cp_commit();
    }

    unsigned long long ar[Fn], ai[Fn];
#pragma unroll
    for (int f = 0; f < Fn; ++f) { ar[f] = 0ull; ai[f] = 0ull; }

    const unsigned long long* sxu =
        reinterpret_cast<const unsigned long long*>(&sx[0][0][0]);
    int t2 = tid;   // u64 index within a 256-float row half

#pragma unroll 4
    for (int c = 0; c < Cn; ++c) {
        cp_wait6();
        __syncthreads();

        int st = c & (STAGES - 1);
        unsigned long long xrc = sxu[st * (2 * Mn / 2) + t2];
        unsigned long long xic = sxu[st * (2 * Mn / 2) + (Mn / 2) + t2];
        unsigned long long nxi = xic ^ 0x8000000080000000ULL;

#pragma unroll
        for (int f = 0; f < Fn; ++f) {
            ulonglong2 w = s2[f * Cn + c];    // broadcast LDS.128
            ar[f] = ffma2(w.x, xrc, ar[f]);
            ar[f] = ffma2(w.y, nxi, ar[f]);
            ai[f] = ffma2(w.x, xic, ai[f]);
            ai[f] = ffma2(w.y, xrc, ai[f]);
        }

        int cn = c + STAGES - 1;
        if (cn < Cn) {
            int sn = cn & (STAGES - 1);
            cp16(sdst0 + sn * (2 * Mn * 4), gsrc + (size_t)cn * LM);
        }
        cp_commit();   // empty groups are legal; keeps wait_group bookkeeping fixed
    }

    float sc = sqrtf(1.0f + (float)l) * (1.0f / 32.0f);
    int m0 = tid * 2;
    float* o_real = out + (size_t)b * Fn * LM + (size_t)l * Mn + m0;
    float* o_imag = o_real + IMAG_OFF;

#pragma unroll
    for (int f = 0; f < Fn; ++f) {
        U64 u;
        u.u = ar[f];
        float2 vr2;
        vr2.x = fmaxf(u.f.x * sc, 0.0f);
        vr2.y = fmaxf(u.f.y * sc, 0.0f);
        *reinterpret_cast<float2*>(o_real + (size_t)f * LM) = vr2;

        u.u = ai[f];
        float2 vi2;
        vi2.x = u.f.x * sc;
        vi2.y = u.f.y * sc;
        *reinterpret_cast<float2*>(o_imag + (size_t)f * LM) = vi2;
    }
}

extern "C" void kernel_launch(void* const* d_in, const int* in_sizes, int n_in,
                              void* d_out, int out_size) {
    const float* x_real = (const float*)d_in[0];
    const float* x_imag = (const float*)d_in[1];
    const float* w_real = (const float*)d_in[2];
    const float* w_imag = (const float*)d_in[3];
    float* out = (float*)d_out;

    sphere_pipe_kernel<<<Bn * Ln, 128>>>(x_real, x_imag, w_real, w_imag, out);
}